// round 14
// baseline (speedup 1.0000x reference)
#include <cuda_runtime.h>

// Problem constants (from reference)
#define S_TOK   131072
#define DIM     512
#define VOCAB   100000
#define K_SLOTS 16        // ranks 0..15 per row; P(count>16) ~ 0 for lambda=0.655

// Scratch (device globals — zero at module load; the update kernel restores the
// all-zero invariant every run, so graph replays are self-consistent).
__device__ int g_counts[VOCAB];          // tokens per vocab row
__device__ int g_slot[VOCAB * K_SLOTS];  // token index per (row, rank). Never needs
                                         // clearing: only ranks < count are read.
__device__ int g_ovf_vidp1[S_TOK];       // overflow sentinel: vid+1 at token pos (0=empty)

// ---------------------------------------------------------------------------
// Kernel 1: histogram + slot placement. 4 tokens per thread via int4 loads
// (4 independent atomic chains per thread, MLP=4). 128-thread blocks -> 256
// blocks spread across all 148 SMs.
// ---------------------------------------------------------------------------
__global__ void compact_kernel(const int4* __restrict__ l2_data4,
                               const int4* __restrict__ l2_idxs4) {
    int i = blockIdx.x * blockDim.x + threadIdx.x;   // i < S_TOK/4
    int4 idx = l2_idxs4[i];
    int4 dat = l2_data4[i];
    int base = i * 4;

    if (idx.x == 1) {
        int r = atomicAdd(&g_counts[dat.x], 1);
        if (r < K_SLOTS) g_slot[dat.x * K_SLOTS + r] = base;
        else             g_ovf_vidp1[base] = dat.x + 1;
    }
    if (idx.y == 1) {
        int r = atomicAdd(&g_counts[dat.y], 1);
        if (r < K_SLOTS) g_slot[dat.y * K_SLOTS + r] = base + 1;
        else             g_ovf_vidp1[base + 1] = dat.y + 1;
    }
    if (idx.z == 1) {
        int r = atomicAdd(&g_counts[dat.z], 1);
        if (r < K_SLOTS) g_slot[dat.z * K_SLOTS + r] = base + 2;
        else             g_ovf_vidp1[base + 2] = dat.z + 1;
    }
    if (idx.w == 1) {
        int r = atomicAdd(&g_counts[dat.w], 1);
        if (r < K_SLOTS) g_slot[dat.w * K_SLOTS + r] = base + 3;
        else             g_ovf_vidp1[base + 3] = dat.w + 1;
    }
}

// ---------------------------------------------------------------------------
// Cold overflow accumulator, quarantined behind a noinline ABI boundary so its
// ballot/ffs loop registers don't inflate the hot kernel's allocation.
// Never executed for this dataset (P(c>16) ~ 0); correct for any input.
// ---------------------------------------------------------------------------
struct OvfAcc { float4 a, b, c, d; };

__device__ __noinline__ OvfAcc overflow_sum(int vp1, int remaining,
                                            const float4* __restrict__ x4,
                                            int lane) {
    OvfAcc r;
    r.a = make_float4(0.f, 0.f, 0.f, 0.f);
    r.b = r.a; r.c = r.a; r.d = r.a;
    for (int b0 = 0; b0 < S_TOK && remaining > 0; b0 += 32) {
        int vpo = g_ovf_vidp1[b0 + lane];
        unsigned m = __ballot_sync(0xFFFFFFFFu, vpo == vp1);
        while (m) {
            int j2 = b0 + (__ffs(m) - 1);
            m &= m - 1;
            const float4* src = x4 + (long)j2 * (DIM / 4);
            float4 a = src[lane];
            float4 b = src[lane + 32];
            float4 d = src[lane + 64];
            float4 e = src[lane + 96];
            r.a.x += a.x; r.a.y += a.y; r.a.z += a.z; r.a.w += a.w;
            r.b.x += b.x; r.b.y += b.y; r.b.z += b.z; r.b.w += b.w;
            r.c.x += d.x; r.c.y += d.y; r.c.z += d.z; r.c.w += d.w;
            r.d.x += e.x; r.d.y += e.y; r.d.z += e.z; r.d.w += e.w;
            if (lane == 0) g_ovf_vidp1[j2] = 0;       // consume + clear
            remaining--;
        }
    }
    return r;
}

// ---------------------------------------------------------------------------
// Kernel 2: update. Warp-per-row over ALL rows (exact grid: VOCAB/8 blocks).
// __launch_bounds__(256, 8): force 32 regs -> 8 blocks/SM (R13 measured 6
// blocks @ 40 regs, occ 52.8%, DRAM 74.6% — residency was the MLP limiter).
//   c==0 -> out = w (streaming copy; 52% of rows — saturates DRAM and hides
//           the gather warps' dependent-load latency)
//   c>=1 -> gather the c token rows from slots, single EMA write
// No atomics, no seed writes: every output byte written exactly once.
// Scratch reset folded in race-free (each warp owns its row's count).
// ---------------------------------------------------------------------------
__global__ void __launch_bounds__(256, 8)
update_kernel(const float4* __restrict__ x4,
              const float4* __restrict__ w4,
              float4* __restrict__ out4) {
    int row  = (blockIdx.x * blockDim.x + threadIdx.x) >> 5;
    int lane = threadIdx.x & 31;

    int c = g_counts[row];                 // uniform across warp
    long base = (long)row * (DIM / 4);

    if (c == 0) {
        float4 a = __ldcs(&w4[base + lane]);
        float4 b = __ldcs(&w4[base + lane + 32]);
        float4 d = __ldcs(&w4[base + lane + 64]);
        float4 e = __ldcs(&w4[base + lane + 96]);
        __stcs(&out4[base + lane],      a);
        __stcs(&out4[base + lane + 32], b);
        __stcs(&out4[base + lane + 64], d);
        __stcs(&out4[base + lane + 96], e);
        return;
    }

    if (lane == 0) g_counts[row] = 0;      // reset for next replay

    // --- gather ranks 0..min(c,K)-1 ---
    float4 s0 = make_float4(0.f, 0.f, 0.f, 0.f);
    float4 s1 = s0, s2 = s0, s3 = s0;

    int ns = (c < K_SLOTS) ? c : K_SLOTS;
    for (int t = 0; t < ns; t++) {
        int tok = g_slot[row * K_SLOTS + t];          // warp-uniform broadcast
        const float4* src = x4 + (long)tok * (DIM / 4);
        float4 a = __ldcs(&src[lane]);
        float4 b = __ldcs(&src[lane + 32]);
        float4 d = __ldcs(&src[lane + 64]);
        float4 e = __ldcs(&src[lane + 96]);
        s0.x += a.x; s0.y += a.y; s0.z += a.z; s0.w += a.w;
        s1.x += b.x; s1.y += b.y; s1.z += b.z; s1.w += b.w;
        s2.x += d.x; s2.y += d.y; s2.z += d.z; s2.w += d.w;
        s3.x += e.x; s3.y += e.y; s3.z += e.z; s3.w += e.w;
    }

    if (c > K_SLOTS) {                     // cold: never taken for this data
        OvfAcc r = overflow_sum(row + 1, c - K_SLOTS, x4, lane);
        s0.x += r.a.x; s0.y += r.a.y; s0.z += r.a.z; s0.w += r.a.w;
        s1.x += r.b.x; s1.y += r.b.y; s1.z += r.b.z; s1.w += r.b.w;
        s2.x += r.c.x; s2.y += r.c.y; s2.z += r.c.z; s2.w += r.c.w;
        s3.x += r.d.x; s3.y += r.d.y; s3.z += r.d.z; s3.w += r.d.w;
    }

    // --- final EMA write ---
    float inv = 0.5f / (float)c;
    float4 w0 = __ldcs(&w4[base + lane]);
    float4 w1 = __ldcs(&w4[base + lane + 32]);
    float4 w2 = __ldcs(&w4[base + lane + 64]);
    float4 w3 = __ldcs(&w4[base + lane + 96]);
    __stcs(&out4[base + lane], make_float4(
        fmaf(s0.x, inv, 0.5f * w0.x), fmaf(s0.y, inv, 0.5f * w0.y),
        fmaf(s0.z, inv, 0.5f * w0.z), fmaf(s0.w, inv, 0.5f * w0.w)));
    __stcs(&out4[base + lane + 32], make_float4(
        fmaf(s1.x, inv, 0.5f * w1.x), fmaf(s1.y, inv, 0.5f * w1.y),
        fmaf(s1.z, inv, 0.5f * w1.z), fmaf(s1.w, inv, 0.5f * w1.w)));
    __stcs(&out4[base + lane + 64], make_float4(
        fmaf(s2.x, inv, 0.5f * w2.x), fmaf(s2.y, inv, 0.5f * w2.y),
        fmaf(s2.z, inv, 0.5f * w2.z), fmaf(s2.w, inv, 0.5f * w2.w)));
    __stcs(&out4[base + lane + 96], make_float4(
        fmaf(s3.x, inv, 0.5f * w3.x), fmaf(s3.y, inv, 0.5f * w3.y),
        fmaf(s3.z, inv, 0.5f * w3.z), fmaf(s3.w, inv, 0.5f * w3.w)));
}

// ---------------------------------------------------------------------------
extern "C" void kernel_launch(void* const* d_in, const int* in_sizes, int n_in,
                              void* d_out, int out_size) {
    const float* out_act   = (const float*)d_in[0];   // [S, D] f32
    const float* l2_weight = (const float*)d_in[1];   // [V, D] f32
    const int*   l2_data   = (const int*)d_in[2];     // [S] i32
    const int*   l2_idxs   = (const int*)d_in[3];     // [S] i32
    float* outp = (float*)d_out;                      // [V, D] f32

    (void)in_sizes; (void)n_in; (void)out_size;

    // 1. histogram + slots (scratch all-zero on entry; 4 tokens/thread,
    //    128-thread blocks -> 256 blocks across 148 SMs)
    compact_kernel<<<S_TOK / 4 / 128, 128>>>((const int4*)l2_data,
                                             (const int4*)l2_idxs);

    // 2. update: c==0 copy + c>=1 gather-EMA + scratch reset (warp-per-row)
    update_kernel<<<VOCAB / 8, 256>>>((const float4*)out_act,
                                      (const float4*)l2_weight,
                                      (float4*)outp);
}

// round 15
// speedup vs baseline: 1.1547x; 1.1547x over previous
#include <cuda_runtime.h>

// Problem constants (from reference)
#define S_TOK   131072
#define DIM     512
#define VOCAB   100000
#define K_SLOTS 16        // ranks 0..15 per row; P(count>16) ~ 0 for lambda=0.655

// Scratch (device globals — zero at module load; the update kernel restores the
// all-zero invariant every run, so graph replays are self-consistent).
__device__ int g_counts[VOCAB];          // tokens per vocab row
__device__ int g_slot[VOCAB * K_SLOTS];  // token index per (row, rank). Never needs
                                         // clearing: only ranks < count are read.
__device__ int g_ovf_vidp1[S_TOK];       // overflow sentinel: vid+1 at token pos (0=empty)

// ---------------------------------------------------------------------------
// Kernel 1: histogram + slot placement. 4 tokens per thread via int4 loads
// (4 independent atomic chains per thread, MLP=4). 128-thread blocks so the
// grid is 256 blocks — ~2 per SM across 148 SMs.
// ---------------------------------------------------------------------------
__global__ void compact_kernel(const int4* __restrict__ l2_data4,
                               const int4* __restrict__ l2_idxs4) {
    int i = blockIdx.x * blockDim.x + threadIdx.x;   // i < S_TOK/4
    int4 idx = l2_idxs4[i];
    int4 dat = l2_data4[i];
    int base = i * 4;

    if (idx.x == 1) {
        int r = atomicAdd(&g_counts[dat.x], 1);
        if (r < K_SLOTS) g_slot[dat.x * K_SLOTS + r] = base;
        else             g_ovf_vidp1[base] = dat.x + 1;
    }
    if (idx.y == 1) {
        int r = atomicAdd(&g_counts[dat.y], 1);
        if (r < K_SLOTS) g_slot[dat.y * K_SLOTS + r] = base + 1;
        else             g_ovf_vidp1[base + 1] = dat.y + 1;
    }
    if (idx.z == 1) {
        int r = atomicAdd(&g_counts[dat.z], 1);
        if (r < K_SLOTS) g_slot[dat.z * K_SLOTS + r] = base + 2;
        else             g_ovf_vidp1[base + 2] = dat.z + 1;
    }
    if (idx.w == 1) {
        int r = atomicAdd(&g_counts[dat.w], 1);
        if (r < K_SLOTS) g_slot[dat.w * K_SLOTS + r] = base + 3;
        else             g_ovf_vidp1[base + 3] = dat.w + 1;
    }
}

// ---------------------------------------------------------------------------
// Kernel 2: update (R13 exact — best measured: 85.1us kernel, 89.5us total).
// Warp-per-row over ALL rows (exact grid: VOCAB/8 blocks of 256).
//   c==0 -> out = w (streaming copy; 52% of rows — saturates DRAM and hides
//           the gather warps' dependent-load latency)
//   c>=1 -> gather the c token rows from slots, single EMA write
// No atomics, no seed writes: every output byte written exactly once, every
// input byte read exactly once (533 MB total = the traffic floor).
// Scratch reset folded in race-free (each warp owns its row's count).
//
// Tuning ledger (all empirically closed):
//   - natural 40 regs / 6 blocks/SM: DRAM 74.6%. Forcing 32 regs / 8 blocks
//     raised occ to 72% but serialized per-thread loads (L1 61%, DRAM 66.7%,
//     +16.6us) — per-thread MLP beats warp count here. Do NOT cap regs.
//   - L2 prefetch of w: -1.7us isolated, +2us in graph-replay steady state.
//   - PDL overlap of compact: +3.7us launch overhead, no overlap realized.
// ---------------------------------------------------------------------------
__global__ void __launch_bounds__(256, 6)
update_kernel(const float4* __restrict__ x4,
              const float4* __restrict__ w4,
              float4* __restrict__ out4) {
    int row  = (blockIdx.x * blockDim.x + threadIdx.x) >> 5;
    int lane = threadIdx.x & 31;

    int c = g_counts[row];                 // uniform across warp
    long base = (long)row * (DIM / 4);

    if (c == 0) {
        float4 a = __ldcs(&w4[base + lane]);
        float4 b = __ldcs(&w4[base + lane + 32]);
        float4 d = __ldcs(&w4[base + lane + 64]);
        float4 e = __ldcs(&w4[base + lane + 96]);
        __stcs(&out4[base + lane],      a);
        __stcs(&out4[base + lane + 32], b);
        __stcs(&out4[base + lane + 64], d);
        __stcs(&out4[base + lane + 96], e);
        return;
    }

    if (lane == 0) g_counts[row] = 0;      // reset for next replay

    // --- gather ranks 0..min(c,K)-1 ---
    float4 s0 = make_float4(0.f, 0.f, 0.f, 0.f);
    float4 s1 = s0, s2 = s0, s3 = s0;

    int ns = (c < K_SLOTS) ? c : K_SLOTS;
    for (int t = 0; t < ns; t++) {
        int tok = g_slot[row * K_SLOTS + t];          // warp-uniform broadcast
        const float4* src = x4 + (long)tok * (DIM / 4);
        float4 a = __ldcs(&src[lane]);
        float4 b = __ldcs(&src[lane + 32]);
        float4 d = __ldcs(&src[lane + 64]);
        float4 e = __ldcs(&src[lane + 96]);
        s0.x += a.x; s0.y += a.y; s0.z += a.z; s0.w += a.w;
        s1.x += b.x; s1.y += b.y; s1.z += b.z; s1.w += b.w;
        s2.x += d.x; s2.y += d.y; s2.z += d.z; s2.w += d.w;
        s3.x += e.x; s3.y += e.y; s3.z += e.z; s3.w += e.w;
    }

    if (c > K_SLOTS) {
        // cold overflow path: correct for any input, never taken for this data
        int remaining = c - K_SLOTS;
        for (int b0 = 0; b0 < S_TOK && remaining > 0; b0 += 32) {
            int vpo = g_ovf_vidp1[b0 + lane];
            unsigned m = __ballot_sync(0xFFFFFFFFu, vpo == row + 1);
            while (m) {
                int j2 = b0 + (__ffs(m) - 1);
                m &= m - 1;
                const float4* src = x4 + (long)j2 * (DIM / 4);
                float4 a = src[lane];
                float4 b = src[lane + 32];
                float4 d = src[lane + 64];
                float4 e = src[lane + 96];
                s0.x += a.x; s0.y += a.y; s0.z += a.z; s0.w += a.w;
                s1.x += b.x; s1.y += b.y; s1.z += b.z; s1.w += b.w;
                s2.x += d.x; s2.y += d.y; s2.z += d.z; s2.w += d.w;
                s3.x += e.x; s3.y += e.y; s3.z += e.z; s3.w += e.w;
                if (lane == 0) g_ovf_vidp1[j2] = 0;   // consume + clear
                remaining--;
            }
        }
    }

    // --- final EMA write ---
    float inv = 0.5f / (float)c;
    float4 w0 = __ldcs(&w4[base + lane]);
    float4 w1 = __ldcs(&w4[base + lane + 32]);
    float4 w2 = __ldcs(&w4[base + lane + 64]);
    float4 w3 = __ldcs(&w4[base + lane + 96]);
    __stcs(&out4[base + lane], make_float4(
        fmaf(s0.x, inv, 0.5f * w0.x), fmaf(s0.y, inv, 0.5f * w0.y),
        fmaf(s0.z, inv, 0.5f * w0.z), fmaf(s0.w, inv, 0.5f * w0.w)));
    __stcs(&out4[base + lane + 32], make_float4(
        fmaf(s1.x, inv, 0.5f * w1.x), fmaf(s1.y, inv, 0.5f * w1.y),
        fmaf(s1.z, inv, 0.5f * w1.z), fmaf(s1.w, inv, 0.5f * w1.w)));
    __stcs(&out4[base + lane + 64], make_float4(
        fmaf(s2.x, inv, 0.5f * w2.x), fmaf(s2.y, inv, 0.5f * w2.y),
        fmaf(s2.z, inv, 0.5f * w2.z), fmaf(s2.w, inv, 0.5f * w2.w)));
    __stcs(&out4[base + lane + 96], make_float4(
        fmaf(s3.x, inv, 0.5f * w3.x), fmaf(s3.y, inv, 0.5f * w3.y),
        fmaf(s3.z, inv, 0.5f * w3.z), fmaf(s3.w, inv, 0.5f * w3.w)));
}

// ---------------------------------------------------------------------------
extern "C" void kernel_launch(void* const* d_in, const int* in_sizes, int n_in,
                              void* d_out, int out_size) {
    const float* out_act   = (const float*)d_in[0];   // [S, D] f32
    const float* l2_weight = (const float*)d_in[1];   // [V, D] f32
    const int*   l2_data   = (const int*)d_in[2];     // [S] i32
    const int*   l2_idxs   = (const int*)d_in[3];     // [S] i32
    float* outp = (float*)d_out;                      // [V, D] f32

    (void)in_sizes; (void)n_in; (void)out_size;

    // 1. histogram + slots (scratch all-zero on entry; 4 tokens/thread,
    //    128-thread blocks -> 256 blocks across 148 SMs)
    compact_kernel<<<S_TOK / 4 / 128, 128>>>((const int4*)l2_data,
                                             (const int4*)l2_idxs);

    // 2. update: c==0 copy + c>=1 gather-EMA + scratch reset (warp-per-row)
    update_kernel<<<VOCAB / 8, 256>>>((const float4*)out_act,
                                      (const float4*)l2_weight,
                                      (float4*)outp);
}